// round 4
// baseline (speedup 1.0000x reference)
#include <cuda_runtime.h>
#include <cuda_bf16.h>
#include <math_constants.h>
#include <cstdint>

#define BB 4
#define TT 2048
#define DM 1024
#define NH 16
#define DH 64

__device__ float g_qkv[(size_t)BB * TT * 3 * DM];   // 96 MB (raw qkv, rope fused later)
__device__ float g_att[(size_t)BB * TT * DM];       // 32 MB

// ===========================================================================
// Helpers
// ===========================================================================
__device__ __forceinline__ uint32_t f2tf32(float f) {
    uint32_t u;
    asm("cvt.rna.tf32.f32 %0, %1;" : "=r"(u) : "f"(f));
    return u;
}

// D += A(16x8,row) * B(8x8,col), tf32 inputs, f32 accum
__device__ __forceinline__ void mma8(float* c, const uint32_t* a,
                                     uint32_t b0, uint32_t b1) {
    asm volatile(
        "mma.sync.aligned.m16n8k8.row.col.f32.tf32.tf32.f32 "
        "{%0,%1,%2,%3}, {%4,%5,%6,%7}, {%8,%9}, {%0,%1,%2,%3};"
        : "+f"(c[0]), "+f"(c[1]), "+f"(c[2]), "+f"(c[3])
        : "r"(a[0]), "r"(a[1]), "r"(a[2]), "r"(a[3]), "r"(b0), "r"(b1));
}

__device__ __forceinline__ uint32_t smem_u32(const void* p) {
    uint32_t a;
    asm("{ .reg .u64 t; cvta.to.shared.u64 t, %1; cvt.u32.u64 %0, t; }"
        : "=r"(a) : "l"(p));
    return a;
}

__device__ __forceinline__ void cpa16(uint32_t s, const void* g) {
    asm volatile("cp.async.ca.shared.global [%0], [%1], 16;" :: "r"(s), "l"(g));
}
#define CPA_COMMIT() asm volatile("cp.async.commit_group;" ::: "memory")
#define CPA_WAIT(n)  asm volatile("cp.async.wait_group %0;" :: "n"(n) : "memory")

// ===========================================================================
// GEMM: C[m][n] = sum_k A[m][k]*W[n][k] + bias[n]
// BM=BN=128, BK=32. 256 threads = 8 warps (4m x 2n), warp tile 32x64.
// ===========================================================================
#define GSTR 36
#define GTILE (128 * GSTR)
#define GSMEM_TOTAL (4 * GTILE * 4)

__global__ void __launch_bounds__(256, 2)
gemm_tc(const float* __restrict__ A, const float* __restrict__ W,
        const float* __restrict__ bias, float* __restrict__ C,
        int M, int N, int K) {
    extern __shared__ float gsm[];
    const int tid  = threadIdx.x;
    const int wid  = tid >> 5;
    const int lane = tid & 31;
    const int g    = lane >> 2;
    const int tig  = lane & 3;
    const int wm   = wid & 3;
    const int wn   = wid >> 2;

    const int m0 = blockIdx.y * 128;
    const int n0 = blockIdx.x * 128;

    const uint32_t sbase = smem_u32(gsm);

    float acc[2][8][4];
    #pragma unroll
    for (int i = 0; i < 2; i++)
        #pragma unroll
        for (int j = 0; j < 8; j++)
            #pragma unroll
            for (int e = 0; e < 4; e++) acc[i][j][e] = 0.f;

    const int NK = K >> 5;

    auto load_stage = [&](int st, int k0) {
        uint32_t sA = sbase + (uint32_t)(st * 2 * GTILE) * 4;
        uint32_t sB = sA + GTILE * 4;
        #pragma unroll
        for (int it = 0; it < 4; it++) {
            int lin = tid + it * 256;
            int r   = lin >> 3;
            int c4  = lin & 7;
            cpa16(sA + (uint32_t)(r * GSTR + c4 * 4) * 4,
                  A + (size_t)(m0 + r) * K + k0 + c4 * 4);
            cpa16(sB + (uint32_t)(r * GSTR + c4 * 4) * 4,
                  W + (size_t)(n0 + r) * K + k0 + c4 * 4);
        }
    };

    load_stage(0, 0);
    CPA_COMMIT();

    for (int kt = 0; kt < NK; kt++) {
        if (kt + 1 < NK) {
            load_stage((kt + 1) & 1, (kt + 1) << 5);
            CPA_COMMIT();
            CPA_WAIT(1);
        } else {
            CPA_WAIT(0);
        }
        __syncthreads();

        const float* sA = gsm + (kt & 1) * 2 * GTILE;
        const float* sB = sA + GTILE;

        #pragma unroll
        for (int s = 0; s < 4; s++) {
            int ks = s * 8;
            uint32_t a[2][4];
            #pragma unroll
            for (int i = 0; i < 2; i++) {
                int rb = wm * 32 + i * 16;
                a[i][0] = f2tf32(sA[(rb + g) * GSTR + ks + tig]);
                a[i][1] = f2tf32(sA[(rb + g + 8) * GSTR + ks + tig]);
                a[i][2] = f2tf32(sA[(rb + g) * GSTR + ks + tig + 4]);
                a[i][3] = f2tf32(sA[(rb + g + 8) * GSTR + ks + tig + 4]);
            }
            #pragma unroll
            for (int j = 0; j < 8; j++) {
                int nb = wn * 64 + j * 8;
                uint32_t b0 = f2tf32(sB[(nb + g) * GSTR + ks + tig]);
                uint32_t b1 = f2tf32(sB[(nb + g) * GSTR + ks + tig + 4]);
                mma8(acc[0][j], a[0], b0, b1);
                mma8(acc[1][j], a[1], b0, b1);
            }
        }
        __syncthreads();
    }

    #pragma unroll
    for (int i = 0; i < 2; i++) {
        int row = m0 + wm * 32 + i * 16 + g;
        #pragma unroll
        for (int j = 0; j < 8; j++) {
            int col = n0 + wn * 64 + j * 8 + 2 * tig;
            float bv0 = bias[col], bv1 = bias[col + 1];
            float2 v0 = make_float2(acc[i][j][0] + bv0, acc[i][j][1] + bv1);
            float2 v1 = make_float2(acc[i][j][2] + bv0, acc[i][j][3] + bv1);
            *(float2*)(C + (size_t)row * N + col) = v0;
            *(float2*)(C + (size_t)(row + 8) * N + col) = v1;
        }
    }
}

// ===========================================================================
// Flash attention v3, tf32 mma.sync, RoPE fused into Q/K staging.
// Grid (T/128, B*H), 256 threads = 8 warps; warp owns 16 query rows.
// K/V tiles (64 keys) staged pre-converted to tf32 in smem, double-buffered.
// ===========================================================================
#define AST 68
#define KVW (64 * AST)          // words per K or V tile buffer
// smem words: Kt[2] (2*KVW) + Vt[2] (2*KVW) + Ps (128*AST)
#define ASMEM_WORDS (4 * KVW + 128 * AST)
#define ASMEM_TOTAL (ASMEM_WORDS * 4)

__global__ void __launch_bounds__(256, 1)
attn_tc(const float* __restrict__ qkv,
        const float* __restrict__ fcos,
        const float* __restrict__ fsin,
        float* __restrict__ att_out) {
    extern __shared__ uint32_t asm32[];
    uint32_t* Kt = asm32;                 // 2 buffers
    uint32_t* Vt = asm32 + 2 * KVW;       // 2 buffers
    float*    Ps = (float*)(asm32 + 4 * KVW);   // 128 x AST (Q staging + P)

    const int tid  = threadIdx.x;
    const int w    = tid >> 5;
    const int lane = tid & 31;
    const int g    = lane >> 2;
    const int tig  = lane & 3;
    const int rb   = w * 16;

    const int b  = blockIdx.y >> 4;
    const int h  = blockIdx.y & 15;
    const int q0 = blockIdx.x * 128;

    const float* base = qkv + (size_t)b * TT * (3 * DM) + h * DH;

    // --- stage Q: rope + scale, fp32 into Ps ---
    #pragma unroll
    for (int it = 0; it < 8; it++) {
        int lin = tid + it * 256;           // 0..2047
        int r = lin >> 4, c4 = lin & 15;
        int t = q0 + r;
        float4 v = *(const float4*)(base + (size_t)t * (3 * DM) + c4 * 4);
        float c0 = fcos[t * 32 + 2 * c4], c1 = fcos[t * 32 + 2 * c4 + 1];
        float s0 = fsin[t * 32 + 2 * c4], s1 = fsin[t * 32 + 2 * c4 + 1];
        float4 o4;
        o4.x = (v.x * c0 - v.y * s0) * 0.125f;
        o4.y = (v.x * s0 + v.y * c0) * 0.125f;
        o4.z = (v.z * c1 - v.w * s1) * 0.125f;
        o4.w = (v.z * s1 + v.w * c1) * 0.125f;
        *(float4*)&Ps[r * AST + c4 * 4] = o4;
    }
    __syncthreads();

    // --- Q fragments (convert once) ---
    uint32_t qa[8][4];
    #pragma unroll
    for (int s = 0; s < 8; s++) {
        int ks = s * 8;
        qa[s][0] = f2tf32(Ps[(rb + g) * AST + ks + tig]);
        qa[s][1] = f2tf32(Ps[(rb + g + 8) * AST + ks + tig]);
        qa[s][2] = f2tf32(Ps[(rb + g) * AST + ks + tig + 4]);
        qa[s][3] = f2tf32(Ps[(rb + g + 8) * AST + ks + tig + 4]);
    }

    // --- K/V staging: rope K, convert both to tf32 ---
    auto stage_kv = [&](int buf, int j0) {
        uint32_t* Kd = Kt + buf * KVW;
        uint32_t* Vd = Vt + buf * KVW;
        #pragma unroll
        for (int it = 0; it < 4; it++) {
            int lin = tid + it * 256;       // 0..1023
            int r = lin >> 4, c4 = lin & 15;
            int t = j0 + r;
            const float* kp = base + (size_t)t * (3 * DM) + c4 * 4;
            float4 kv = *(const float4*)(kp + DM);
            float4 vv = *(const float4*)(kp + 2 * DM);
            float c0 = fcos[t * 32 + 2 * c4], c1 = fcos[t * 32 + 2 * c4 + 1];
            float s0 = fsin[t * 32 + 2 * c4], s1 = fsin[t * 32 + 2 * c4 + 1];
            uint4 ku, vu;
            ku.x = f2tf32(kv.x * c0 - kv.y * s0);
            ku.y = f2tf32(kv.x * s0 + kv.y * c0);
            ku.z = f2tf32(kv.z * c1 - kv.w * s1);
            ku.w = f2tf32(kv.z * s1 + kv.w * c1);
            vu.x = f2tf32(vv.x); vu.y = f2tf32(vv.y);
            vu.z = f2tf32(vv.z); vu.w = f2tf32(vv.w);
            *(uint4*)&Kd[r * AST + c4 * 4] = ku;
            *(uint4*)&Vd[r * AST + c4 * 4] = vu;
        }
    };

    float o[8][4];
    #pragma unroll
    for (int j = 0; j < 8; j++)
        #pragma unroll
        for (int e = 0; e < 4; e++) o[j][e] = 0.f;
    float m0v = -CUDART_INF_F, m1v = -CUDART_INF_F;
    float l0 = 0.f, l1 = 0.f;

    const int ntiles = 2 * blockIdx.x + 2;

    stage_kv(0, 0);
    __syncthreads();

    for (int tile = 0; tile < ntiles; tile++) {
        const int j0  = tile * 64;
        const int cur = tile & 1;
        const uint32_t* Kc = Kt + cur * KVW;
        const uint32_t* Vc = Vt + cur * KVW;
        const bool active = (j0 <= q0 + rb + 15);   // warp-uniform

        float sacc[8][4];
        if (active) {
            #pragma unroll
            for (int j = 0; j < 8; j++)
                #pragma unroll
                for (int e = 0; e < 4; e++) sacc[j][e] = 0.f;
            #pragma unroll
            for (int s = 0; s < 8; s++) {
                int ks = s * 8;
                #pragma unroll
                for (int j = 0; j < 8; j++) {
                    uint32_t b0 = Kc[(j * 8 + g) * AST + ks + tig];
                    uint32_t b1 = Kc[(j * 8 + g) * AST + ks + tig + 4];
                    mma8(sacc[j], qa[s], b0, b1);
                }
            }
        }

        // prefetch next K/V tile (overlaps softmax + PV below)
        if (tile + 1 < ntiles) stage_kv(cur ^ 1, j0 + 64);

        if (active) {
            const int row0 = q0 + rb + g;
            const int row1 = row0 + 8;
            if (j0 + 63 > q0 + rb) {   // diagonal warp-tile: mask
                #pragma unroll
                for (int j = 0; j < 8; j++) {
                    int col = j0 + j * 8 + 2 * tig;
                    if (col > row0)     sacc[j][0] = -CUDART_INF_F;
                    if (col + 1 > row0) sacc[j][1] = -CUDART_INF_F;
                    if (col > row1)     sacc[j][2] = -CUDART_INF_F;
                    if (col + 1 > row1) sacc[j][3] = -CUDART_INF_F;
                }
            }

            float rmax0 = -CUDART_INF_F, rmax1 = -CUDART_INF_F;
            #pragma unroll
            for (int j = 0; j < 8; j++) {
                rmax0 = fmaxf(rmax0, fmaxf(sacc[j][0], sacc[j][1]));
                rmax1 = fmaxf(rmax1, fmaxf(sacc[j][2], sacc[j][3]));
            }
            rmax0 = fmaxf(rmax0, __shfl_xor_sync(0xffffffffu, rmax0, 1));
            rmax0 = fmaxf(rmax0, __shfl_xor_sync(0xffffffffu, rmax0, 2));
            rmax1 = fmaxf(rmax1, __shfl_xor_sync(0xffffffffu, rmax1, 1));
            rmax1 = fmaxf(rmax1, __shfl_xor_sync(0xffffffffu, rmax1, 2));

            float nm0 = fmaxf(m0v, rmax0);
            float nm1 = fmaxf(m1v, rmax1);
            float sc0 = __expf(m0v - nm0);
            float sc1 = __expf(m1v - nm1);

            float ls0 = 0.f, ls1 = 0.f;
            #pragma unroll
            for (int j = 0; j < 8; j++) {
                float p0 = __expf(sacc[j][0] - nm0);
                float p1 = __expf(sacc[j][1] - nm0);
                float p2 = __expf(sacc[j][2] - nm1);
                float p3 = __expf(sacc[j][3] - nm1);
                ls0 += p0 + p1;
                ls1 += p2 + p3;
                *(float2*)&Ps[(rb + g) * AST + j * 8 + 2 * tig]     = make_float2(p0, p1);
                *(float2*)&Ps[(rb + g + 8) * AST + j * 8 + 2 * tig] = make_float2(p2, p3);
            }
            ls0 += __shfl_xor_sync(0xffffffffu, ls0, 1);
            ls0 += __shfl_xor_sync(0xffffffffu, ls0, 2);
            ls1 += __shfl_xor_sync(0xffffffffu, ls1, 1);
            ls1 += __shfl_xor_sync(0xffffffffu, ls1, 2);

            m0v = nm0; m1v = nm1;
            l0 = l0 * sc0 + ls0;
            l1 = l1 * sc1 + ls1;
            #pragma unroll
            for (int j = 0; j < 8; j++) {
                o[j][0] *= sc0; o[j][1] *= sc0;
                o[j][2] *= sc1; o[j][3] *= sc1;
            }
            __syncwarp();

            #pragma unroll
            for (int s = 0; s < 8; s++) {
                int ks = s * 8;
                uint32_t pa[4];
                pa[0] = f2tf32(Ps[(rb + g) * AST + ks + tig]);
                pa[1] = f2tf32(Ps[(rb + g + 8) * AST + ks + tig]);
                pa[2] = f2tf32(Ps[(rb + g) * AST + ks + tig + 4]);
                pa[3] = f2tf32(Ps[(rb + g + 8) * AST + ks + tig + 4]);
                #pragma unroll
                for (int dj = 0; dj < 8; dj++) {
                    uint32_t b0 = Vc[(ks + tig) * AST + dj * 8 + g];
                    uint32_t b1 = Vc[(ks + tig + 4) * AST + dj * 8 + g];
                    mma8(o[dj], pa, b0, b1);
                }
            }
        }
        __syncthreads();
    }

    float inv0 = 1.f / l0, inv1 = 1.f / l1;
    int row0 = q0 + rb + g;
    float* op0 = att_out + ((size_t)(b * TT + row0)) * DM + h * DH;
    float* op1 = op0 + (size_t)8 * DM;
    #pragma unroll
    for (int dj = 0; dj < 8; dj++) {
        int col = dj * 8 + 2 * tig;
        *(float2*)&op0[col] = make_float2(o[dj][0] * inv0, o[dj][1] * inv0);
        *(float2*)&op1[col] = make_float2(o[dj][2] * inv1, o[dj][3] * inv1);
    }
}

// ---------------------------------------------------------------------------
// kernel_launch
// Inputs: 0:x  1:mask(unused)  2:freqs_cos  3:freqs_sin
//         4:qkv_w  5:qkv_b  6:proj_w  7:proj_b
// ---------------------------------------------------------------------------
extern "C" void kernel_launch(void* const* d_in, const int* in_sizes, int n_in,
                              void* d_out, int out_size) {
    const float* x      = (const float*)d_in[0];
    const float* fcos   = (const float*)d_in[2];
    const float* fsin   = (const float*)d_in[3];
    const float* qkv_w  = (const float*)d_in[4];
    const float* qkv_b  = (const float*)d_in[5];
    const float* proj_w = (const float*)d_in[6];
    const float* proj_b = (const float*)d_in[7];
    float* out = (float*)d_out;

    float *qkv, *att;
    cudaGetSymbolAddress((void**)&qkv, g_qkv);
    cudaGetSymbolAddress((void**)&att, g_att);

    cudaFuncSetAttribute(gemm_tc, cudaFuncAttributeMaxDynamicSharedMemorySize,
                         GSMEM_TOTAL);
    cudaFuncSetAttribute(attn_tc, cudaFuncAttributeMaxDynamicSharedMemorySize,
                         ASMEM_TOTAL);

    const int M = BB * TT;   // 8192

    // 1) QKV GEMM
    {
        dim3 grid(3 * DM / 128, M / 128);
        gemm_tc<<<grid, 256, GSMEM_TOTAL>>>(x, qkv_w, qkv_b, qkv, M, 3 * DM, DM);
    }
    // 2) Causal attention (RoPE fused)
    {
        dim3 grid(TT / 128, BB * NH);
        attn_tc<<<grid, 256, ASMEM_TOTAL>>>(qkv, fcos, fsin, att);
    }
    // 3) Output projection
    {
        dim3 grid(DM / 128, M / 128);
        gemm_tc<<<grid, 256, GSMEM_TOTAL>>>(att, proj_w, proj_b, out, M, DM, DM);
    }
}

// round 5
// speedup vs baseline: 1.1469x; 1.1469x over previous
#include <cuda_runtime.h>
#include <math_constants.h>
#include <cstdint>

#define BB 4
#define TT 2048
#define DM 1024
#define NH 16
#define DH 64

// Scratch buffers (all float arrays; "prepped" = tf32-rounded bits, k-pair interleaved)
__device__ float g_qkv [(size_t)BB * TT * 3 * DM];  // raw qkv gemm output
__device__ float g_qkv2[(size_t)BB * TT * 3 * DM];  // prepped q(rope,scaled),k(rope),v
__device__ float g_att [(size_t)BB * TT * DM];      // attention out, prepped for proj
__device__ float g_xT  [(size_t)BB * TT * DM];      // prepped x
__device__ float g_wq  [(size_t)3 * DM * DM];       // prepped qkv_w
__device__ float g_wp  [(size_t)DM * DM];           // prepped proj_w

// ===========================================================================
// Helpers
// ===========================================================================
__device__ __forceinline__ uint32_t f2tf32(float f) {
    uint32_t u;
    asm("cvt.rna.tf32.f32 %0, %1;" : "=r"(u) : "f"(f));
    return u;
}
__device__ __forceinline__ float rna(float f) { return __uint_as_float(f2tf32(f)); }

// D += A(16x8,row) * B(8x8,col), tf32 inputs, f32 accum
__device__ __forceinline__ void mma8(float* c, const uint32_t* a,
                                     uint32_t b0, uint32_t b1) {
    asm volatile(
        "mma.sync.aligned.m16n8k8.row.col.f32.tf32.tf32.f32 "
        "{%0,%1,%2,%3}, {%4,%5,%6,%7}, {%8,%9}, {%0,%1,%2,%3};"
        : "+f"(c[0]), "+f"(c[1]), "+f"(c[2]), "+f"(c[3])
        : "r"(a[0]), "r"(a[1]), "r"(a[2]), "r"(a[3]), "r"(b0), "r"(b1));
}

__device__ __forceinline__ uint32_t smem_u32(const void* p) {
    uint32_t a;
    asm("{ .reg .u64 t; cvta.to.shared.u64 t, %1; cvt.u32.u64 %0, t; }"
        : "=r"(a) : "l"(p));
    return a;
}
__device__ __forceinline__ void cpa16(uint32_t s, const void* g) {
    asm volatile("cp.async.ca.shared.global [%0], [%1], 16;" :: "r"(s), "l"(g));
}
#define CPA_COMMIT() asm volatile("cp.async.commit_group;" ::: "memory")
#define CPA_WAIT(n)  asm volatile("cp.async.wait_group %0;" :: "n"(n) : "memory")

// interleave permutation within 8-k groups: pairs (k, k+4) become adjacent
__device__ __forceinline__ int perm8(int k) {
    return (k & ~7) | (2 * (k & 3)) | ((k >> 2) & 1);
}

// ===========================================================================
// prep_plain: tf32-round + k-pair interleave, 8 consecutive elements/thread
// ===========================================================================
__global__ void prep_plain(const float* __restrict__ src, float* __restrict__ dst,
                           int n8) {
    int i = blockIdx.x * blockDim.x + threadIdx.x;
    if (i >= n8) return;
    const float4* s = (const float4*)src + (size_t)i * 2;
    float4 v0 = s[0], v1 = s[1];
    float4 o0, o1;
    o0.x = rna(v0.x); o0.y = rna(v1.x); o0.z = rna(v0.y); o0.w = rna(v1.y);
    o1.x = rna(v0.z); o1.y = rna(v1.z); o1.z = rna(v0.w); o1.w = rna(v1.w);
    float4* d = (float4*)dst + (size_t)i * 2;
    d[0] = o0; d[1] = o1;
}

// ===========================================================================
// prep_qkv: q -> rope*0.125, tf32, interleave ; k -> rope, tf32, interleave ;
//           v -> tf32, plain. 8 elements per thread.
// ===========================================================================
__global__ void prep_qkv(const float* __restrict__ src, float* __restrict__ dst,
                         const float* __restrict__ fcos,
                         const float* __restrict__ fsin) {
    int i = blockIdx.x * blockDim.x + threadIdx.x;   // 0 .. 3*BB*TT*DM/8-1
    size_t e = (size_t)i * 8;
    int row = (int)(e / (3 * DM));
    int col = (int)(e - (size_t)row * (3 * DM));
    int sec = col >> 10;          // 0 q, 1 k, 2 v
    int d   = col & 63;
    int t   = row & (TT - 1);

    const float4* s = (const float4*)(src + e);
    float4 v0 = s[0], v1 = s[1];
    float4 o0, o1;
    if (sec < 2) {
        int ci = t * 32 + (d >> 1);
        float c0 = fcos[ci], c1 = fcos[ci + 1], c2 = fcos[ci + 2], c3 = fcos[ci + 3];
        float s0 = fsin[ci], s1 = fsin[ci + 1], s2 = fsin[ci + 2], s3 = fsin[ci + 3];
        float sc = (sec == 0) ? 0.125f : 1.f;
        float r0 = (v0.x * c0 - v0.y * s0) * sc, r1 = (v0.x * s0 + v0.y * c0) * sc;
        float r2 = (v0.z * c1 - v0.w * s1) * sc, r3 = (v0.z * s1 + v0.w * c1) * sc;
        float r4 = (v1.x * c2 - v1.y * s2) * sc, r5 = (v1.x * s2 + v1.y * c2) * sc;
        float r6 = (v1.z * c3 - v1.w * s3) * sc, r7 = (v1.z * s3 + v1.w * c3) * sc;
        o0.x = rna(r0); o0.y = rna(r4); o0.z = rna(r1); o0.w = rna(r5);
        o1.x = rna(r2); o1.y = rna(r6); o1.z = rna(r3); o1.w = rna(r7);
    } else {
        o0.x = rna(v0.x); o0.y = rna(v0.y); o0.z = rna(v0.z); o0.w = rna(v0.w);
        o1.x = rna(v1.x); o1.y = rna(v1.y); o1.z = rna(v1.z); o1.w = rna(v1.w);
    }
    float4* dp = (float4*)(dst + e);
    dp[0] = o0; dp[1] = o1;
}

// ===========================================================================
// GEMM v4: C = A @ W^T + bias.  A,W prepped (tf32 bits, k-interleaved).
// CTA 128x128, 128 threads = 4 warps (2m x 2n), warp tile 64x64, BK=32.
// cp.async double-buffered, all fragment loads LDS.64, zero cvt.
// ===========================================================================
#define GSTR 40                      // floats per smem row (160B, 16B-aligned, %32==8)
#define GTILEW (128 * GSTR)
#define GSMEM_TOTAL (4 * GTILEW * 4) // 2 stages x (A+B) = 81920 B

__global__ void __launch_bounds__(128, 2)
gemm_tc(const float* __restrict__ A, const float* __restrict__ W,
        const float* __restrict__ bias, float* __restrict__ C,
        int M, int N, int K) {
    extern __shared__ float gsm[];
    const int tid  = threadIdx.x;
    const int wid  = tid >> 5;
    const int lane = tid & 31;
    const int g    = lane >> 2;
    const int tig  = lane & 3;
    const int wm   = wid & 1;
    const int wn   = wid >> 1;

    const int m0 = blockIdx.y * 128;
    const int n0 = blockIdx.x * 128;
    const uint32_t sbase = smem_u32(gsm);

    float acc[4][8][4];
    #pragma unroll
    for (int i = 0; i < 4; i++)
        #pragma unroll
        for (int j = 0; j < 8; j++)
            #pragma unroll
            for (int e = 0; e < 4; e++) acc[i][j][e] = 0.f;

    const int NK = K >> 5;

    auto load_stage = [&](int st, int k0) {
        #pragma unroll
        for (int it = 0; it < 16; it++) {
            int lin   = tid + it * 128;      // 0..2047
            int which = lin >> 10;           // 0 = A, 1 = B
            int r     = (lin & 1023) >> 3;   // 0..127
            int c4    = lin & 7;             // 16B chunk
            const float* src = which
                ? W + (size_t)(n0 + r) * K + k0 + c4 * 4
                : A + (size_t)(m0 + r) * K + k0 + c4 * 4;
            cpa16(sbase + (uint32_t)((st * 2 + which) * GTILEW + r * GSTR + c4 * 4) * 4,
                  src);
        }
    };

    load_stage(0, 0);
    CPA_COMMIT();

    for (int kt = 0; kt < NK; kt++) {
        if (kt + 1 < NK) {
            load_stage((kt + 1) & 1, (kt + 1) << 5);
            CPA_COMMIT();
            CPA_WAIT(1);
        } else {
            CPA_WAIT(0);
        }
        __syncthreads();

        const float* sA = gsm + (kt & 1) * 2 * GTILEW;
        const float* sB = sA + GTILEW;

        #pragma unroll
        for (int s = 0; s < 4; s++) {
            int ks = s * 8;
            uint32_t a[4][4];
            #pragma unroll
            for (int i = 0; i < 4; i++) {
                int r = wm * 64 + i * 16 + g;
                uint2 lo = *(const uint2*)&sA[r * GSTR + ks + 2 * tig];
                uint2 hi = *(const uint2*)&sA[(r + 8) * GSTR + ks + 2 * tig];
                a[i][0] = lo.x; a[i][1] = hi.x; a[i][2] = lo.y; a[i][3] = hi.y;
            }
            #pragma unroll
            for (int j = 0; j < 8; j++) {
                int n = wn * 64 + j * 8 + g;
                uint2 b = *(const uint2*)&sB[n * GSTR + ks + 2 * tig];
                #pragma unroll
                for (int i = 0; i < 4; i++) mma8(acc[i][j], a[i], b.x, b.y);
            }
        }
        __syncthreads();
    }

    #pragma unroll
    for (int i = 0; i < 4; i++) {
        int row = m0 + wm * 64 + i * 16 + g;
        #pragma unroll
        for (int j = 0; j < 8; j++) {
            int col = n0 + wn * 64 + j * 8 + 2 * tig;
            float bv0 = bias[col], bv1 = bias[col + 1];
            *(float2*)(C + (size_t)row * N + col) =
                make_float2(acc[i][j][0] + bv0, acc[i][j][1] + bv1);
            *(float2*)(C + (size_t)(row + 8) * N + col) =
                make_float2(acc[i][j][2] + bv0, acc[i][j][3] + bv1);
        }
    }
}

// ===========================================================================
// Flash attention v5: prepped inputs, cp.async staging, LDS.64 frags, no cvt.
// Grid (T/128, B*H), 256 threads = 8 warps; warp owns 16 query rows.
// Output written tf32+interleaved for the proj GEMM.
// ===========================================================================
#define AST 72
#define KVW (64 * AST)
#define ASMEM_WORDS (4 * KVW + 128 * AST)   // Kt[2], Vt[2], Ps
#define ASMEM_TOTAL (ASMEM_WORDS * 4)       // 110592 B

__global__ void __launch_bounds__(256, 1)
attn_tc(const float* __restrict__ qkv, float* __restrict__ att_out) {
    extern __shared__ float asmf[];
    float* Kt = asmf;
    float* Vt = asmf + 2 * KVW;
    float* Ps = asmf + 4 * KVW;
    const uint32_t sbase = smem_u32(asmf);

    const int tid  = threadIdx.x;
    const int w    = tid >> 5;
    const int lane = tid & 31;
    const int g    = lane >> 2;
    const int tig  = lane & 3;
    const int rb   = w * 16;

    const int b  = blockIdx.y >> 4;
    const int h  = blockIdx.y & 15;
    const int q0 = blockIdx.x * 128;

    const float* base = qkv + (size_t)b * TT * (3 * DM) + h * DH;

    // --- stage Q (prepped: rope+scale+tf32+interleave) ---
    #pragma unroll
    for (int it = 0; it < 8; it++) {
        int lin = tid + it * 256;            // 0..2047
        int r = lin >> 4, c4 = lin & 15;
        cpa16(sbase + (uint32_t)(4 * KVW + r * AST + c4 * 4) * 4,
              base + (size_t)(q0 + r) * (3 * DM) + c4 * 4);
    }
    CPA_COMMIT();

    auto stage_kv = [&](int buf, int j0) {
        #pragma unroll
        for (int it = 0; it < 8; it++) {
            int lin   = tid + it * 256;      // 0..2047
            int which = lin >> 10;           // 0 K, 1 V
            int r  = (lin & 1023) >> 4;
            int c4 = lin & 15;
            const float* src = base + (size_t)(j0 + r) * (3 * DM)
                             + (which ? 2 * DM : DM) + c4 * 4;
            cpa16(sbase + (uint32_t)((which ? 2 * KVW : 0) + buf * KVW
                                     + r * AST + c4 * 4) * 4, src);
        }
    };

    stage_kv(0, 0);
    CPA_COMMIT();
    CPA_WAIT(1);        // Q group done
    __syncthreads();

    // --- Q fragments (LDS.64, interleaved pairs) ---
    const uint32_t* Pu = (const uint32_t*)Ps;
    uint32_t qa[8][4];
    #pragma unroll
    for (int s = 0; s < 8; s++) {
        int ks = s * 8;
        uint2 lo = *(const uint2*)&Pu[(rb + g) * AST + ks + 2 * tig];
        uint2 hi = *(const uint2*)&Pu[(rb + g + 8) * AST + ks + 2 * tig];
        qa[s][0] = lo.x; qa[s][1] = hi.x; qa[s][2] = lo.y; qa[s][3] = hi.y;
    }

    float o[8][4];
    #pragma unroll
    for (int j = 0; j < 8; j++)
        #pragma unroll
        for (int e = 0; e < 4; e++) o[j][e] = 0.f;
    float m0v = -CUDART_INF_F, m1v = -CUDART_INF_F;
    float l0 = 0.f, l1 = 0.f;

    const int ntiles = 2 * blockIdx.x + 2;

    for (int tile = 0; tile < ntiles; tile++) {
        const int j0  = tile * 64;
        const int cur = tile & 1;

        if (tile + 1 < ntiles) {
            stage_kv(cur ^ 1, j0 + 64);
            CPA_COMMIT();
            CPA_WAIT(1);
        } else {
            CPA_WAIT(0);
        }
        __syncthreads();

        const uint32_t* Kc = (const uint32_t*)(Kt + cur * KVW);
        const uint32_t* Vc = (const uint32_t*)(Vt + cur * KVW);
        const bool active = (j0 <= q0 + rb + 15);   // warp-uniform

        if (active) {
            // S = Q @ K^T
            float sacc[8][4];
            #pragma unroll
            for (int j = 0; j < 8; j++)
                #pragma unroll
                for (int e = 0; e < 4; e++) sacc[j][e] = 0.f;
            #pragma unroll
            for (int s = 0; s < 8; s++) {
                int ks = s * 8;
                #pragma unroll
                for (int j = 0; j < 8; j++) {
                    uint2 bb = *(const uint2*)&Kc[(j * 8 + g) * AST + ks + 2 * tig];
                    mma8(sacc[j], qa[s], bb.x, bb.y);
                }
            }

            const int row0 = q0 + rb + g;
            const int row1 = row0 + 8;
            if (j0 + 63 > q0 + rb) {   // diagonal warp-tile
                #pragma unroll
                for (int j = 0; j < 8; j++) {
                    int col = j0 + j * 8 + 2 * tig;
                    if (col > row0)     sacc[j][0] = -CUDART_INF_F;
                    if (col + 1 > row0) sacc[j][1] = -CUDART_INF_F;
                    if (col > row1)     sacc[j][2] = -CUDART_INF_F;
                    if (col + 1 > row1) sacc[j][3] = -CUDART_INF_F;
                }
            }

            float rmax0 = -CUDART_INF_F, rmax1 = -CUDART_INF_F;
            #pragma unroll
            for (int j = 0; j < 8; j++) {
                rmax0 = fmaxf(rmax0, fmaxf(sacc[j][0], sacc[j][1]));
                rmax1 = fmaxf(rmax1, fmaxf(sacc[j][2], sacc[j][3]));
            }
            rmax0 = fmaxf(rmax0, __shfl_xor_sync(0xffffffffu, rmax0, 1));
            rmax0 = fmaxf(rmax0, __shfl_xor_sync(0xffffffffu, rmax0, 2));
            rmax1 = fmaxf(rmax1, __shfl_xor_sync(0xffffffffu, rmax1, 1));
            rmax1 = fmaxf(rmax1, __shfl_xor_sync(0xffffffffu, rmax1, 2));

            float nm0 = fmaxf(m0v, rmax0);
            float nm1 = fmaxf(m1v, rmax1);
            float sc0 = __expf(m0v - nm0);
            float sc1 = __expf(m1v - nm1);

            float ls0 = 0.f, ls1 = 0.f;
            #pragma unroll
            for (int j = 0; j < 8; j++) {
                float p0 = __expf(sacc[j][0] - nm0);
                float p1 = __expf(sacc[j][1] - nm0);
                float p2 = __expf(sacc[j][2] - nm1);
                float p3 = __expf(sacc[j][3] - nm1);
                ls0 += p0 + p1;
                ls1 += p2 + p3;
                *(float2*)&Ps[(rb + g) * AST + j * 8 + 2 * tig]     = make_float2(p0, p1);
                *(float2*)&Ps[(rb + g + 8) * AST + j * 8 + 2 * tig] = make_float2(p2, p3);
            }
            ls0 += __shfl_xor_sync(0xffffffffu, ls0, 1);
            ls0 += __shfl_xor_sync(0xffffffffu, ls0, 2);
            ls1 += __shfl_xor_sync(0xffffffffu, ls1, 1);
            ls1 += __shfl_xor_sync(0xffffffffu, ls1, 2);

            m0v = nm0; m1v = nm1;
            l0 = l0 * sc0 + ls0;
            l1 = l1 * sc1 + ls1;
            #pragma unroll
            for (int j = 0; j < 8; j++) {
                o[j][0] *= sc0; o[j][1] *= sc0;
                o[j][2] *= sc1; o[j][3] *= sc1;
            }
            __syncwarp();

            // O += P @ V   (P raw bits -> tf32 truncation; V prepped tf32)
            #pragma unroll
            for (int s = 0; s < 8; s++) {
                int ks = s * 8;
                uint32_t pa[4];
                pa[0] = Pu[(rb + g) * AST + ks + tig];
                pa[1] = Pu[(rb + g + 8) * AST + ks + tig];
                pa[2] = Pu[(rb + g) * AST + ks + tig + 4];
                pa[3] = Pu[(rb + g + 8) * AST + ks + tig + 4];
                #pragma unroll
                for (int dj = 0; dj < 8; dj++) {
                    uint32_t b0 = Vc[(ks + tig) * AST + dj * 8 + g];
                    uint32_t b1 = Vc[(ks + tig + 4) * AST + dj * 8 + g];
                    mma8(o[dj], pa, b0, b1);
                }
            }
        }
        __syncthreads();
    }

    // normalize + store tf32-rounded, k-interleaved (A-operand of proj GEMM)
    float inv0 = 1.f / l0, inv1 = 1.f / l1;
    int row0 = q0 + rb + g;
    float* op0 = att_out + ((size_t)(b * TT + row0)) * DM + h * DH;
    float* op1 = op0 + (size_t)8 * DM;
    #pragma unroll
    for (int dj = 0; dj < 8; dj++) {
        int c  = dj * 8 + 2 * tig;
        int p0 = perm8(c), p1 = perm8(c + 1);
        op0[p0] = rna(o[dj][0] * inv0);
        op0[p1] = rna(o[dj][1] * inv0);
        op1[p0] = rna(o[dj][2] * inv1);
        op1[p1] = rna(o[dj][3] * inv1);
    }
}

// ---------------------------------------------------------------------------
// kernel_launch
// Inputs: 0:x  1:mask(unused)  2:freqs_cos  3:freqs_sin
//         4:qkv_w  5:qkv_b  6:proj_w  7:proj_b
// ---------------------------------------------------------------------------
extern "C" void kernel_launch(void* const* d_in, const int* in_sizes, int n_in,
                              void* d_out, int out_size) {
    const float* x      = (const float*)d_in[0];
    const float* fcos   = (const float*)d_in[2];
    const float* fsin   = (const float*)d_in[3];
    const float* qkv_w  = (const float*)d_in[4];
    const float* qkv_b  = (const float*)d_in[5];
    const float* proj_w = (const float*)d_in[6];
    const float* proj_b = (const float*)d_in[7];
    float* out = (float*)d_out;

    float *qkv, *qkv2, *att, *xT, *wq, *wp;
    cudaGetSymbolAddress((void**)&qkv,  g_qkv);
    cudaGetSymbolAddress((void**)&qkv2, g_qkv2);
    cudaGetSymbolAddress((void**)&att,  g_att);
    cudaGetSymbolAddress((void**)&xT,   g_xT);
    cudaGetSymbolAddress((void**)&wq,   g_wq);
    cudaGetSymbolAddress((void**)&wp,   g_wp);

    cudaFuncSetAttribute(gemm_tc, cudaFuncAttributeMaxDynamicSharedMemorySize,
                         GSMEM_TOTAL);
    cudaFuncSetAttribute(attn_tc, cudaFuncAttributeMaxDynamicSharedMemorySize,
                         ASMEM_TOTAL);

    const int M = BB * TT;   // 8192

    // 0) operand prep: tf32 + k-pair interleave
    prep_plain<<<(M * DM / 8) / 256, 256>>>(x, xT, M * DM / 8);
    prep_plain<<<(3 * DM * DM / 8) / 256, 256>>>(qkv_w, wq, 3 * DM * DM / 8);
    prep_plain<<<(DM * DM / 8) / 256, 256>>>(proj_w, wp, DM * DM / 8);

    // 1) QKV GEMM -> raw fp32 qkv
    {
        dim3 grid(3 * DM / 128, M / 128);
        gemm_tc<<<grid, 128, GSMEM_TOTAL>>>(xT, wq, qkv_b, qkv, M, 3 * DM, DM);
    }
    // 2) prep qkv: rope+scale+tf32+interleave (q,k), tf32 (v)
    prep_qkv<<<(M * 3 * DM / 8) / 256, 256>>>(qkv, qkv2, fcos, fsin);

    // 3) causal attention -> prepped att
    {
        dim3 grid(TT / 128, BB * NH);
        attn_tc<<<grid, 256, ASMEM_TOTAL>>>(qkv2, att);
    }
    // 4) output projection -> d_out
    {
        dim3 grid(DM / 128, M / 128);
        gemm_tc<<<grid, 128, GSMEM_TOTAL>>>(att, wp, proj_b, out, M, DM, DM);
    }
}